// round 10
// baseline (speedup 1.0000x reference)
#include <cuda_runtime.h>
#include <math.h>

// ---------------------------------------------------------------------------
// TrLaplacianDP: out = embs + noise, where noise[0:300] are the first 300
// accepted samples of a truncated-Laplacian rejection scan over (sgn, u).
//
// R10: SINGLE kernel. Block 0 computes the noise vector (log-free mask:
// |r|<=A <=> u >= 1-2/sqrt(300); logf only for the ~300 stored values) and
// release-publishes g_flag. All other blocks prefetch their embs float4s
// (independent work), acquire-spin on g_flag, then add+store. The last
// block to finish resets flag/counter so every graph replay is identical.
// Removes the second graph node and PDL's whole-grid-completion wait.
// ---------------------------------------------------------------------------

#define EMBS_DIM 300
#define BLK      1024
#define GRID     1200
#define IT       8
#define STRIDE   (GRID * BLK)        // 1228800 = 75 * 16384
#define NCHUNK   (BLK * 4)           // 4096 samples per scan chunk

__device__ __align__(16) float g_noise[304];   // 75 float4 + pad
__device__ int g_flag = 0;    // 0 -> noise not ready; 1 -> ready
__device__ int g_done = 0;    // completed-block counter (for replay reset)

__device__ __forceinline__ float sign_of(float x) {
    return (x > 0.0f) ? 1.0f : ((x < 0.0f) ? -1.0f : 0.0f);
}

// ---------------------------------------------------------------------------
// Noise scan (block 0 only): ordered rejection scan into g_noise.
// ---------------------------------------------------------------------------
__device__ void scan_noise(const float* __restrict__ sgn,
                           const float* __restrict__ u, int n) {
    const double SCALE_D = 2.0 * 0.005 * sqrt(300.0) / 1.0;
    const float  SCALE_F = (float)SCALE_D;
    const float  A_F     = (float)(-SCALE_D * log(1.0 - 2.0 * 1.0 / sqrt(300.0)));
    const float  U_THR   = (float)(1.0 - 2.0 / sqrt(300.0));   // exp(-A/SCALE)
    const float  BAND    = 2e-5f;

    __shared__ int s_wsum[32];
    __shared__ int s_carry, s_total;

    const int tid  = threadIdx.x;
    const int lane = tid & 31;
    const int wid  = tid >> 5;

    if (tid < 304) g_noise[tid] = 0.0f;
    if (tid == 0) s_carry = 0;
    __syncthreads();

    for (int base = 0; base < n; base += NCHUNK) {
        const int i0 = base + tid * 4;
        float sv[4], uv[4];
        bool  have[4], m[4], rdone[4];
        float rv[4];

        if (i0 + 3 < n) {
            const float4 s4 = *reinterpret_cast<const float4*>(sgn + i0);
            const float4 u4 = *reinterpret_cast<const float4*>(u + i0);
            sv[0]=s4.x; sv[1]=s4.y; sv[2]=s4.z; sv[3]=s4.w;
            uv[0]=u4.x; uv[1]=u4.y; uv[2]=u4.z; uv[3]=u4.w;
            have[0]=have[1]=have[2]=have[3]=true;
        } else {
            #pragma unroll
            for (int j = 0; j < 4; ++j) {
                const int i = i0 + j;
                have[j] = (i < n);
                sv[j] = have[j] ? sgn[i] : 0.0f;
                uv[j] = have[j] ? u[i]   : 0.0f;   // u=0 -> fast reject
            }
        }

        int cnt = 0;
        #pragma unroll
        for (int j = 0; j < 4; ++j) {
            rdone[j] = false; rv[j] = 0.0f;
            if (fabsf(uv[j] - U_THR) < BAND || sv[j] == 0.0f) {
                // Exact path (rare): same semantics as passing kernels.
                const float s = sign_of(sv[j]);
                float r = (-SCALE_F * s) * logf(uv[j]);
                if (fabsf(fabsf(r) - A_F) < 1e-4f)
                    r = (-SCALE_F * s) * (float)log((double)uv[j]);
                m[j] = have[j] && (r >= -A_F) && (r <= A_F);
                rv[j] = r; rdone[j] = true;
            } else {
                m[j] = have[j] && (uv[j] >= U_THR);   // log-free mask
            }
            cnt += m[j] ? 1 : 0;
        }

        int incl = cnt;
        #pragma unroll
        for (int o = 1; o < 32; o <<= 1) {
            const int v = __shfl_up_sync(0xffffffffu, incl, o);
            if (lane >= o) incl += v;
        }
        if (lane == 31) s_wsum[wid] = incl;
        __syncthreads();

        if (wid == 0) {
            const int v = s_wsum[lane];
            int iv = v;
            #pragma unroll
            for (int o = 1; o < 32; o <<= 1) {
                const int x = __shfl_up_sync(0xffffffffu, iv, o);
                if (lane >= o) iv += x;
            }
            s_wsum[lane] = iv - v;
            if (lane == 31) s_total = iv;
        }
        __syncthreads();

        int pos = s_carry + s_wsum[wid] + (incl - cnt);
        #pragma unroll
        for (int j = 0; j < 4; ++j) {
            if (m[j]) {
                if (pos < EMBS_DIM) {
                    float r = rv[j];
                    if (!rdone[j])
                        r = (-SCALE_F * sign_of(sv[j])) * logf(uv[j]);
                    g_noise[pos] = r;
                }
                ++pos;
            }
        }
        __syncthreads();
        if (tid == 0) s_carry += s_total;
        __syncthreads();
        if (s_carry >= EMBS_DIM) break;          // uniform
    }
}

// ---------------------------------------------------------------------------
// Fused kernel (exact shape): block 0 scans noise + publishes; others
// prefetch embs, acquire-spin, add, store. Last block resets flag state.
// ---------------------------------------------------------------------------
__global__ void __launch_bounds__(BLK, 1) fused_kernel(
        const float* __restrict__ embs,
        const float* __restrict__ sgn,
        const float* __restrict__ u,
        float* __restrict__ out, int nsamp) {
    const float4* __restrict__ in4  = reinterpret_cast<const float4*>(embs);
    float4* __restrict__       out4 = reinterpret_cast<float4*>(out);

    const int tid = threadIdx.x;
    const int v0  = blockIdx.x * BLK + tid;

    if (blockIdx.x == 0) {
        // ---- Producer block: noise scan, then release-publish. ----
        scan_noise(sgn, u, nsamp);
        __threadfence();                 // make this thread's writes visible
        __syncthreads();                 // all threads' fences done
        if (tid == 0) atomicExch(&g_flag, 1);
        __syncthreads();

        const float4 nz = reinterpret_cast<const float4*>(g_noise)[v0 % 75];
        #pragma unroll
        for (int k = 0; k < IT; ++k) {
            const int vi = v0 + k * STRIDE;
            float4 t = __ldcs(&in4[vi]);
            t.x += nz.x; t.y += nz.y; t.z += nz.z; t.w += nz.w;
            __stcs(&out4[vi], t);
        }
    } else {
        // ---- Consumer blocks: prefetch embs (independent of noise). ----
        float4 e[IT];
        #pragma unroll
        for (int k = 0; k < IT; ++k)
            e[k] = __ldcs(&in4[v0 + k * STRIDE]);

        // Acquire-spin (one thread; others park at the barrier).
        if (tid == 0) {
            while (atomicAdd(&g_flag, 0) == 0) __nanosleep(64);
        }
        __syncthreads();
        __threadfence();                 // acquire: order g_noise reads

        const float4 nz = reinterpret_cast<const float4*>(g_noise)[v0 % 75];
        #pragma unroll
        for (int k = 0; k < IT; ++k) {
            float4 t = e[k];
            t.x += nz.x; t.y += nz.y; t.z += nz.z; t.w += nz.w;
            __stcs(&out4[v0 + k * STRIDE], t);
        }
    }

    // ---- Replay-reset protocol: last finishing block clears state. ----
    __syncthreads();
    if (tid == 0) {
        const int prev = atomicAdd(&g_done, 1);
        if (prev == (int)gridDim.x - 1) {
            g_done = 0;
            atomicExch(&g_flag, 0);
            __threadfence();
        }
    }
}

// ---------------------------------------------------------------------------
// Fallback path for non-exact shapes: R9's two-kernel PDL structure.
// ---------------------------------------------------------------------------
__global__ void __launch_bounds__(1024) noise_kernel(const float* __restrict__ sgn,
                                                     const float* __restrict__ u,
                                                     int n) {
    cudaTriggerProgrammaticLaunchCompletion();
    scan_noise(sgn, u, n);
}

__global__ void __launch_bounds__(256) add_general_kernel(
        const float* __restrict__ embs, float* __restrict__ out,
        int n4, int n) {
    cudaGridDependencySynchronize();

    const float4* __restrict__ in4  = reinterpret_cast<const float4*>(embs);
    float4* __restrict__       out4 = reinterpret_cast<float4*>(out);

    const int stride = gridDim.x * blockDim.x;       // multiple of 75
    const int v0     = blockIdx.x * blockDim.x + threadIdx.x;
    const float4 nz  = reinterpret_cast<const float4*>(g_noise)[v0 % 75];

    for (int v = v0; v < n4; v += 8 * stride) {
        #pragma unroll
        for (int k = 0; k < 8; ++k) {
            const int vi = v + k * stride;
            if (vi < n4) {
                float4 t = __ldcs(&in4[vi]);
                t.x += nz.x; t.y += nz.y; t.z += nz.z; t.w += nz.w;
                __stcs(&out4[vi], t);
            }
        }
    }
    const int tail_start = n4 * 4;
    for (int i = tail_start + v0; i < n; i += stride)
        out[i] = embs[i] + g_noise[i % EMBS_DIM];
}

// ---------------------------------------------------------------------------
extern "C" void kernel_launch(void* const* d_in, const int* in_sizes, int n_in,
                              void* d_out, int out_size) {
    const float* embs = (const float*)d_in[0];
    const float* sgn  = (const float*)d_in[1];
    const float* u    = (const float*)d_in[2];
    float* out        = (float*)d_out;

    const int nsamp = in_sizes[1];
    const int n  = out_size;
    const int n4 = n / 4;

    if (n == n4 * 4 && n4 == GRID * BLK * IT) {
        fused_kernel<<<GRID, BLK>>>(embs, sgn, u, out, nsamp);
    } else {
        noise_kernel<<<1, 1024>>>(sgn, u, nsamp);
        int grid = (n4 + 256 * 8 - 1) / (256 * 8);
        grid = ((grid + 74) / 75) * 75;             // stride % 75 == 0
        if (grid < 75) grid = 75;
        add_general_kernel<<<grid, 256>>>(embs, out, n4, n);
    }
}

// round 11
// speedup vs baseline: 1.1550x; 1.1550x over previous
#include <cuda_runtime.h>
#include <math.h>

// ---------------------------------------------------------------------------
// TrLaplacianDP: out = embs + noise, where noise[0:300] are the first 300
// accepted samples of a truncated-Laplacian rejection scan over (sgn, u).
//
// R11: single-kernel flag design with the PROVEN stream geometry
// (4800 x 256-thread blocks, 8 float4/thread — the 44.4us/74%-DRAM shape).
// Block 0 runs the log-free noise scan (1024-sample chunks, ~3 chunks) and
// release-publishes g_flag; consumer blocks prefetch embs, poll g_flag with
// __ldcg + nanosleep, then add+store. Last finishing block resets the flag
// state so every graph replay is identical.
// ---------------------------------------------------------------------------

#define EMBS_DIM 300
#define BLK      256
#define GRID     4800
#define IT       8
#define STRIDE   (GRID * BLK)        // 1228800 = 75 * 16384
#define NCHUNK   (BLK * 4)           // 1024 samples per scan chunk

__device__ __align__(16) float g_noise[304];   // 75 float4 + pad
__device__ int g_flag = 0;    // 0 -> noise not ready; 1 -> ready
__device__ int g_done = 0;    // completed-block counter (replay reset)

__device__ __forceinline__ float sign_of(float x) {
    return (x > 0.0f) ? 1.0f : ((x < 0.0f) ? -1.0f : 0.0f);
}

// ---------------------------------------------------------------------------
// Noise scan (one 256-thread block): ordered rejection scan into g_noise.
// Log-free mask: |r| <= A  <=>  u >= 1 - 2/sqrt(300). logf only for stored
// values; boundary band (|u-thr|<2e-5 or sgn==0) uses the exact log path.
// ---------------------------------------------------------------------------
__device__ void scan_noise(const float* __restrict__ sgn,
                           const float* __restrict__ u, int n) {
    const double SCALE_D = 2.0 * 0.005 * sqrt(300.0) / 1.0;
    const float  SCALE_F = (float)SCALE_D;
    const float  A_F     = (float)(-SCALE_D * log(1.0 - 2.0 * 1.0 / sqrt(300.0)));
    const float  U_THR   = (float)(1.0 - 2.0 / sqrt(300.0));   // exp(-A/SCALE)
    const float  BAND    = 2e-5f;

    __shared__ int s_wsum[8];
    __shared__ int s_carry, s_total;

    const int tid  = threadIdx.x;
    const int lane = tid & 31;
    const int wid  = tid >> 5;         // 8 warps

    for (int i = tid; i < 304; i += BLK) g_noise[i] = 0.0f;
    if (tid == 0) s_carry = 0;
    __syncthreads();

    for (int base = 0; base < n; base += NCHUNK) {
        const int i0 = base + tid * 4;
        float sv[4], uv[4];
        bool  have[4], m[4], rdone[4];
        float rv[4];

        if (i0 + 3 < n) {
            const float4 s4 = *reinterpret_cast<const float4*>(sgn + i0);
            const float4 u4 = *reinterpret_cast<const float4*>(u + i0);
            sv[0]=s4.x; sv[1]=s4.y; sv[2]=s4.z; sv[3]=s4.w;
            uv[0]=u4.x; uv[1]=u4.y; uv[2]=u4.z; uv[3]=u4.w;
            have[0]=have[1]=have[2]=have[3]=true;
        } else {
            #pragma unroll
            for (int j = 0; j < 4; ++j) {
                const int i = i0 + j;
                have[j] = (i < n);
                sv[j] = have[j] ? sgn[i] : 0.0f;
                uv[j] = have[j] ? u[i]   : 0.0f;   // u=0 -> fast reject
            }
        }

        int cnt = 0;
        #pragma unroll
        for (int j = 0; j < 4; ++j) {
            rdone[j] = false; rv[j] = 0.0f;
            if (fabsf(uv[j] - U_THR) < BAND || sv[j] == 0.0f) {
                // Exact path (rare): identical to passing kernels.
                const float s = sign_of(sv[j]);
                float r = (-SCALE_F * s) * logf(uv[j]);
                if (fabsf(fabsf(r) - A_F) < 1e-4f)
                    r = (-SCALE_F * s) * (float)log((double)uv[j]);
                m[j] = have[j] && (r >= -A_F) && (r <= A_F);
                rv[j] = r; rdone[j] = true;
            } else {
                m[j] = have[j] && (uv[j] >= U_THR);   // log-free mask
            }
            cnt += m[j] ? 1 : 0;
        }

        int incl = cnt;
        #pragma unroll
        for (int o = 1; o < 32; o <<= 1) {
            const int v = __shfl_up_sync(0xffffffffu, incl, o);
            if (lane >= o) incl += v;
        }
        if (lane == 31) s_wsum[wid] = incl;
        __syncthreads();

        if (wid == 0 && lane < 8) {
            const int v = s_wsum[lane];
            int iv = v;
            #pragma unroll
            for (int o = 1; o < 8; o <<= 1) {
                const int x = __shfl_up_sync(0x000000ffu, iv, o);
                if (lane >= o) iv += x;
            }
            s_wsum[lane] = iv - v;
            if (lane == 7) s_total = iv;
        }
        __syncthreads();

        int pos = s_carry + s_wsum[wid] + (incl - cnt);
        #pragma unroll
        for (int j = 0; j < 4; ++j) {
            if (m[j]) {
                if (pos < EMBS_DIM) {
                    float r = rv[j];
                    if (!rdone[j])
                        r = (-SCALE_F * sign_of(sv[j])) * logf(uv[j]);
                    g_noise[pos] = r;
                }
                ++pos;
            }
        }
        __syncthreads();
        if (tid == 0) s_carry += s_total;
        __syncthreads();
        if (s_carry >= EMBS_DIM) break;          // uniform
    }
}

// ---------------------------------------------------------------------------
// Fused kernel (exact shape).
// ---------------------------------------------------------------------------
__global__ void __launch_bounds__(BLK) fused_kernel(
        const float* __restrict__ embs,
        const float* __restrict__ sgn,
        const float* __restrict__ u,
        float* __restrict__ out, int nsamp) {
    const float4* __restrict__ in4  = reinterpret_cast<const float4*>(embs);
    float4* __restrict__       out4 = reinterpret_cast<float4*>(out);

    const int tid = threadIdx.x;
    const int v0  = blockIdx.x * BLK + tid;

    if (blockIdx.x == 0) {
        // ---- Producer block: scan, release-publish, then own add slice. ----
        scan_noise(sgn, u, nsamp);
        __threadfence();
        __syncthreads();
        if (tid == 0) atomicExch(&g_flag, 1);

        const float4 nz = reinterpret_cast<const float4*>(g_noise)[v0 % 75];
        #pragma unroll
        for (int k = 0; k < IT; ++k) {
            const int vi = v0 + k * STRIDE;
            float4 t = __ldcs(&in4[vi]);
            t.x += nz.x; t.y += nz.y; t.z += nz.z; t.w += nz.w;
            __stcs(&out4[vi], t);
        }
    } else {
        // ---- Consumers: prefetch embs (independent of noise). ----
        float4 e[IT];
        #pragma unroll
        for (int k = 0; k < IT; ++k)
            e[k] = __ldcs(&in4[v0 + k * STRIDE]);

        // Poll (one thread per block; plain L2 load, no atomic traffic).
        if (tid == 0) {
            while (__ldcg(&g_flag) == 0) __nanosleep(128);
        }
        __syncthreads();
        __threadfence();                 // acquire: order g_noise reads

        const float4 nz = reinterpret_cast<const float4*>(g_noise)[v0 % 75];
        #pragma unroll
        for (int k = 0; k < IT; ++k) {
            float4 t = e[k];
            t.x += nz.x; t.y += nz.y; t.z += nz.z; t.w += nz.w;
            __stcs(&out4[v0 + k * STRIDE], t);
        }
    }

    // ---- Replay-reset protocol: last finishing block clears state. ----
    __syncthreads();
    if (tid == 0) {
        const int prev = atomicAdd(&g_done, 1);
        if (prev == (int)gridDim.x - 1) {
            g_done = 0;
            atomicExch(&g_flag, 0);
            __threadfence();
        }
    }
}

// ---------------------------------------------------------------------------
// Fallback for non-exact shapes: R9's two-kernel PDL structure.
// ---------------------------------------------------------------------------
__global__ void __launch_bounds__(256) noise_kernel(const float* __restrict__ sgn,
                                                    const float* __restrict__ u,
                                                    int n) {
    cudaTriggerProgrammaticLaunchCompletion();
    scan_noise(sgn, u, n);
}

__global__ void __launch_bounds__(256) add_general_kernel(
        const float* __restrict__ embs, float* __restrict__ out,
        int n4, int n) {
    cudaGridDependencySynchronize();

    const float4* __restrict__ in4  = reinterpret_cast<const float4*>(embs);
    float4* __restrict__       out4 = reinterpret_cast<float4*>(out);

    const int stride = gridDim.x * blockDim.x;       // multiple of 75
    const int v0     = blockIdx.x * blockDim.x + threadIdx.x;
    const float4 nz  = reinterpret_cast<const float4*>(g_noise)[v0 % 75];

    for (int v = v0; v < n4; v += 8 * stride) {
        #pragma unroll
        for (int k = 0; k < 8; ++k) {
            const int vi = v + k * stride;
            if (vi < n4) {
                float4 t = __ldcs(&in4[vi]);
                t.x += nz.x; t.y += nz.y; t.z += nz.z; t.w += nz.w;
                __stcs(&out4[vi], t);
            }
        }
    }
    const int tail_start = n4 * 4;
    for (int i = tail_start + v0; i < n; i += stride)
        out[i] = embs[i] + g_noise[i % EMBS_DIM];
}

// ---------------------------------------------------------------------------
extern "C" void kernel_launch(void* const* d_in, const int* in_sizes, int n_in,
                              void* d_out, int out_size) {
    const float* embs = (const float*)d_in[0];
    const float* sgn  = (const float*)d_in[1];
    const float* u    = (const float*)d_in[2];
    float* out        = (float*)d_out;

    const int nsamp = in_sizes[1];
    const int n  = out_size;
    const int n4 = n / 4;

    if (n == n4 * 4 && n4 == GRID * BLK * IT) {
        fused_kernel<<<GRID, BLK>>>(embs, sgn, u, out, nsamp);
    } else {
        noise_kernel<<<1, 256>>>(sgn, u, nsamp);
        int grid = (n4 + 256 * 8 - 1) / (256 * 8);
        grid = ((grid + 74) / 75) * 75;             // stride % 75 == 0
        if (grid < 75) grid = 75;
        add_general_kernel<<<grid, 256>>>(embs, out, n4, n);
    }
}

// round 12
// speedup vs baseline: 1.1600x; 1.0043x over previous
#include <cuda_runtime.h>
#include <math.h>

// ---------------------------------------------------------------------------
// TrLaplacianDP: out = embs + noise, where noise[0:300] are the first 300
// accepted samples of a truncated-Laplacian rejection scan over (sgn, u).
//
// R11: single-kernel flag design with the PROVEN stream geometry
// (4800 x 256-thread blocks, 8 float4/thread — the 44.4us/74%-DRAM shape).
// Block 0 runs the log-free noise scan (1024-sample chunks, ~3 chunks) and
// release-publishes g_flag; consumer blocks prefetch embs, poll g_flag with
// __ldcg + nanosleep, then add+store. Last finishing block resets the flag
// state so every graph replay is identical.
// ---------------------------------------------------------------------------

#define EMBS_DIM 300
#define BLK      256
#define GRID     4800
#define IT       8
#define STRIDE   (GRID * BLK)        // 1228800 = 75 * 16384
#define NCHUNK   (BLK * 4)           // 1024 samples per scan chunk

__device__ __align__(16) float g_noise[304];   // 75 float4 + pad
__device__ int g_flag = 0;    // 0 -> noise not ready; 1 -> ready
__device__ int g_done = 0;    // completed-block counter (replay reset)

__device__ __forceinline__ float sign_of(float x) {
    return (x > 0.0f) ? 1.0f : ((x < 0.0f) ? -1.0f : 0.0f);
}

// ---------------------------------------------------------------------------
// Noise scan (one 256-thread block): ordered rejection scan into g_noise.
// Log-free mask: |r| <= A  <=>  u >= 1 - 2/sqrt(300). logf only for stored
// values; boundary band (|u-thr|<2e-5 or sgn==0) uses the exact log path.
// ---------------------------------------------------------------------------
__device__ void scan_noise(const float* __restrict__ sgn,
                           const float* __restrict__ u, int n) {
    const double SCALE_D = 2.0 * 0.005 * sqrt(300.0) / 1.0;
    const float  SCALE_F = (float)SCALE_D;
    const float  A_F     = (float)(-SCALE_D * log(1.0 - 2.0 * 1.0 / sqrt(300.0)));
    const float  U_THR   = (float)(1.0 - 2.0 / sqrt(300.0));   // exp(-A/SCALE)
    const float  BAND    = 2e-5f;

    __shared__ int s_wsum[8];
    __shared__ int s_carry, s_total;

    const int tid  = threadIdx.x;
    const int lane = tid & 31;
    const int wid  = tid >> 5;         // 8 warps

    for (int i = tid; i < 304; i += BLK) g_noise[i] = 0.0f;
    if (tid == 0) s_carry = 0;
    __syncthreads();

    for (int base = 0; base < n; base += NCHUNK) {
        const int i0 = base + tid * 4;
        float sv[4], uv[4];
        bool  have[4], m[4], rdone[4];
        float rv[4];

        if (i0 + 3 < n) {
            const float4 s4 = *reinterpret_cast<const float4*>(sgn + i0);
            const float4 u4 = *reinterpret_cast<const float4*>(u + i0);
            sv[0]=s4.x; sv[1]=s4.y; sv[2]=s4.z; sv[3]=s4.w;
            uv[0]=u4.x; uv[1]=u4.y; uv[2]=u4.z; uv[3]=u4.w;
            have[0]=have[1]=have[2]=have[3]=true;
        } else {
            #pragma unroll
            for (int j = 0; j < 4; ++j) {
                const int i = i0 + j;
                have[j] = (i < n);
                sv[j] = have[j] ? sgn[i] : 0.0f;
                uv[j] = have[j] ? u[i]   : 0.0f;   // u=0 -> fast reject
            }
        }

        int cnt = 0;
        #pragma unroll
        for (int j = 0; j < 4; ++j) {
            rdone[j] = false; rv[j] = 0.0f;
            if (fabsf(uv[j] - U_THR) < BAND || sv[j] == 0.0f) {
                // Exact path (rare): identical to passing kernels.
                const float s = sign_of(sv[j]);
                float r = (-SCALE_F * s) * logf(uv[j]);
                if (fabsf(fabsf(r) - A_F) < 1e-4f)
                    r = (-SCALE_F * s) * (float)log((double)uv[j]);
                m[j] = have[j] && (r >= -A_F) && (r <= A_F);
                rv[j] = r; rdone[j] = true;
            } else {
                m[j] = have[j] && (uv[j] >= U_THR);   // log-free mask
            }
            cnt += m[j] ? 1 : 0;
        }

        int incl = cnt;
        #pragma unroll
        for (int o = 1; o < 32; o <<= 1) {
            const int v = __shfl_up_sync(0xffffffffu, incl, o);
            if (lane >= o) incl += v;
        }
        if (lane == 31) s_wsum[wid] = incl;
        __syncthreads();

        if (wid == 0 && lane < 8) {
            const int v = s_wsum[lane];
            int iv = v;
            #pragma unroll
            for (int o = 1; o < 8; o <<= 1) {
                const int x = __shfl_up_sync(0x000000ffu, iv, o);
                if (lane >= o) iv += x;
            }
            s_wsum[lane] = iv - v;
            if (lane == 7) s_total = iv;
        }
        __syncthreads();

        int pos = s_carry + s_wsum[wid] + (incl - cnt);
        #pragma unroll
        for (int j = 0; j < 4; ++j) {
            if (m[j]) {
                if (pos < EMBS_DIM) {
                    float r = rv[j];
                    if (!rdone[j])
                        r = (-SCALE_F * sign_of(sv[j])) * logf(uv[j]);
                    g_noise[pos] = r;
                }
                ++pos;
            }
        }
        __syncthreads();
        if (tid == 0) s_carry += s_total;
        __syncthreads();
        if (s_carry >= EMBS_DIM) break;          // uniform
    }
}

// ---------------------------------------------------------------------------
// Fused kernel (exact shape).
// ---------------------------------------------------------------------------
__global__ void __launch_bounds__(BLK) fused_kernel(
        const float* __restrict__ embs,
        const float* __restrict__ sgn,
        const float* __restrict__ u,
        float* __restrict__ out, int nsamp) {
    const float4* __restrict__ in4  = reinterpret_cast<const float4*>(embs);
    float4* __restrict__       out4 = reinterpret_cast<float4*>(out);

    const int tid = threadIdx.x;
    const int v0  = blockIdx.x * BLK + tid;

    if (blockIdx.x == 0) {
        // ---- Producer block: scan, release-publish, then own add slice. ----
        scan_noise(sgn, u, nsamp);
        __threadfence();
        __syncthreads();
        if (tid == 0) atomicExch(&g_flag, 1);

        const float4 nz = reinterpret_cast<const float4*>(g_noise)[v0 % 75];
        #pragma unroll
        for (int k = 0; k < IT; ++k) {
            const int vi = v0 + k * STRIDE;
            float4 t = __ldcs(&in4[vi]);
            t.x += nz.x; t.y += nz.y; t.z += nz.z; t.w += nz.w;
            __stcs(&out4[vi], t);
        }
    } else {
        // ---- Consumers: prefetch embs (independent of noise). ----
        float4 e[IT];
        #pragma unroll
        for (int k = 0; k < IT; ++k)
            e[k] = __ldcs(&in4[v0 + k * STRIDE]);

        // Poll (one thread per block; plain L2 load, no atomic traffic).
        if (tid == 0) {
            while (__ldcg(&g_flag) == 0) __nanosleep(128);
        }
        __syncthreads();
        __threadfence();                 // acquire: order g_noise reads

        const float4 nz = reinterpret_cast<const float4*>(g_noise)[v0 % 75];
        #pragma unroll
        for (int k = 0; k < IT; ++k) {
            float4 t = e[k];
            t.x += nz.x; t.y += nz.y; t.z += nz.z; t.w += nz.w;
            __stcs(&out4[v0 + k * STRIDE], t);
        }
    }

    // ---- Replay-reset protocol: last finishing block clears state. ----
    __syncthreads();
    if (tid == 0) {
        const int prev = atomicAdd(&g_done, 1);
        if (prev == (int)gridDim.x - 1) {
            g_done = 0;
            atomicExch(&g_flag, 0);
            __threadfence();
        }
    }
}

// ---------------------------------------------------------------------------
// Fallback for non-exact shapes: R9's two-kernel PDL structure.
// ---------------------------------------------------------------------------
__global__ void __launch_bounds__(256) noise_kernel(const float* __restrict__ sgn,
                                                    const float* __restrict__ u,
                                                    int n) {
    cudaTriggerProgrammaticLaunchCompletion();
    scan_noise(sgn, u, n);
}

__global__ void __launch_bounds__(256) add_general_kernel(
        const float* __restrict__ embs, float* __restrict__ out,
        int n4, int n) {
    cudaGridDependencySynchronize();

    const float4* __restrict__ in4  = reinterpret_cast<const float4*>(embs);
    float4* __restrict__       out4 = reinterpret_cast<float4*>(out);

    const int stride = gridDim.x * blockDim.x;       // multiple of 75
    const int v0     = blockIdx.x * blockDim.x + threadIdx.x;
    const float4 nz  = reinterpret_cast<const float4*>(g_noise)[v0 % 75];

    for (int v = v0; v < n4; v += 8 * stride) {
        #pragma unroll
        for (int k = 0; k < 8; ++k) {
            const int vi = v + k * stride;
            if (vi < n4) {
                float4 t = __ldcs(&in4[vi]);
                t.x += nz.x; t.y += nz.y; t.z += nz.z; t.w += nz.w;
                __stcs(&out4[vi], t);
            }
        }
    }
    const int tail_start = n4 * 4;
    for (int i = tail_start + v0; i < n; i += stride)
        out[i] = embs[i] + g_noise[i % EMBS_DIM];
}

// ---------------------------------------------------------------------------
extern "C" void kernel_launch(void* const* d_in, const int* in_sizes, int n_in,
                              void* d_out, int out_size) {
    const float* embs = (const float*)d_in[0];
    const float* sgn  = (const float*)d_in[1];
    const float* u    = (const float*)d_in[2];
    float* out        = (float*)d_out;

    const int nsamp = in_sizes[1];
    const int n  = out_size;
    const int n4 = n / 4;

    if (n == n4 * 4 && n4 == GRID * BLK * IT) {
        fused_kernel<<<GRID, BLK>>>(embs, sgn, u, out, nsamp);
    } else {
        noise_kernel<<<1, 256>>>(sgn, u, nsamp);
        int grid = (n4 + 256 * 8 - 1) / (256 * 8);
        grid = ((grid + 74) / 75) * 75;             // stride % 75 == 0
        if (grid < 75) grid = 75;
        add_general_kernel<<<grid, 256>>>(embs, out, n4, n);
    }
}